// round 8
// baseline (speedup 1.0000x reference)
#include <cuda_runtime.h>
#include <cuda_fp16.h>
#include <math.h>

typedef unsigned int u32;

// Problem constants
#define B_   16
#define H_   56
#define W_   56
#define C_   512
#define WS_  7
#define NH_  16
#define HD_  32
#define HID_ 2048
#define N_   49
#define NW_  64
#define L_   (H_ * W_)          // 3136
#define ROWS_ (B_ * L_)         // 50176
#define QKVC_ 1536
#define SCALE_ 0.17677669529663687f
#define EPS_ 1e-5f

// Scratch (device globals: allocation-free)
__device__ __half g_h  [ROWS_ * C_];
__device__ __half g_qkv[ROWS_ * QKVC_];
__device__ __half g_ao [ROWS_ * C_];
__device__ float  g_x2 [ROWS_ * C_];
__device__ __half g_hid[ROWS_ * HID_];
__device__ __half g_wtqkv[QKVC_ * C_];   // [1536][512]  (Wq^T | Wk^T | Wv^T)
__device__ __half g_wtp  [C_ * C_];
__device__ __half g_wt1  [HID_ * C_];
__device__ __half g_wt2  [C_ * HID_];
__device__ float  g_bqkv [QKVC_];

// ---------------------------------------------------------------------------
// Helpers
// ---------------------------------------------------------------------------
__device__ __forceinline__ void cp_async16(u32 saddr, const void* gptr) {
    asm volatile("cp.async.cg.shared.global [%0], [%1], 16;" :: "r"(saddr), "l"(gptr));
}
#define CP_COMMIT() asm volatile("cp.async.commit_group;")
#define CP_WAIT(n)  asm volatile("cp.async.wait_group %0;" :: "n"(n))

#define MMA_F16(ac, ar, b0, b1)                                                 \
    asm volatile(                                                               \
        "mma.sync.aligned.m16n8k16.row.col.f32.f16.f16.f32 "                    \
        "{%0,%1,%2,%3},{%4,%5,%6,%7},{%8,%9},{%0,%1,%2,%3};"                    \
        : "+f"(ac[0]), "+f"(ac[1]), "+f"(ac[2]), "+f"(ac[3])                    \
        : "r"(ar[0]), "r"(ar[1]), "r"(ar[2]), "r"(ar[3]), "r"(b0), "r"(b1))

#define LDSM_X4(r, a)                                                           \
    asm volatile("ldmatrix.sync.aligned.m8n8.x4.shared.b16 {%0,%1,%2,%3}, [%4];"\
        : "=r"((r)[0]), "=r"((r)[1]), "=r"((r)[2]), "=r"((r)[3]) : "r"(a))

__device__ __forceinline__ u32 smem_u32(const void* p) {
    return (u32)__cvta_generic_to_shared(p);
}

// ---------------------------------------------------------------------------
// Transpose + fp16 convert: dst[Cc][R] = half(src[R][Cc]^T)
// ---------------------------------------------------------------------------
__global__ __launch_bounds__(256) void transpose_kernel(
    const float* __restrict__ src, __half* __restrict__ dst, int R, int Cc)
{
    __shared__ float tile[32][33];
    int bx = blockIdx.x * 32, by = blockIdx.y * 32;
    int tx = threadIdx.x, ty = threadIdx.y;   // 32 x 8
    #pragma unroll
    for (int i = 0; i < 32; i += 8)
        tile[ty + i][tx] = src[(size_t)(by + ty + i) * Cc + bx + tx];
    __syncthreads();
    #pragma unroll
    for (int i = 0; i < 32; i += 8)
        dst[(size_t)(bx + ty + i) * R + by + tx] = __float2half_rn(tile[tx][ty + i]);
}

__global__ void pack_bias_kernel(const float* __restrict__ bq,
                                 const float* __restrict__ bk,
                                 const float* __restrict__ bv,
                                 float* __restrict__ dst)
{
    int i = blockIdx.x * 256 + threadIdx.x;
    if (i < QKVC_)
        dst[i] = i < 512 ? bq[i] : (i < 1024 ? bk[i - 512] : bv[i - 1024]);
}

// ---------------------------------------------------------------------------
// LayerNorm: fp32 in, fp16 out
// ---------------------------------------------------------------------------
__global__ __launch_bounds__(128) void ln_kernel(const float* __restrict__ x,
                                                 const float* __restrict__ g,
                                                 const float* __restrict__ b,
                                                 __half* __restrict__ out) {
    int row = blockIdx.x;
    const float4* xr = (const float4*)(x + (size_t)row * C_);
    float4 v = xr[threadIdx.x];
    float s  = v.x + v.y + v.z + v.w;
    float s2 = v.x * v.x + v.y * v.y + v.z * v.z + v.w * v.w;
    #pragma unroll
    for (int o = 16; o; o >>= 1) {
        s  += __shfl_xor_sync(0xffffffffu, s, o);
        s2 += __shfl_xor_sync(0xffffffffu, s2, o);
    }
    __shared__ float sm[4], sm2[4];
    int warp = threadIdx.x >> 5;
    if ((threadIdx.x & 31) == 0) { sm[warp] = s; sm2[warp] = s2; }
    __syncthreads();
    s  = sm[0] + sm[1] + sm[2] + sm[3];
    s2 = sm2[0] + sm2[1] + sm2[2] + sm2[3];
    float mu   = s * (1.0f / C_);
    float var  = s2 * (1.0f / C_) - mu * mu;
    float rstd = rsqrtf(var + EPS_);
    float4 gg = ((const float4*)g)[threadIdx.x];
    float4 bb = ((const float4*)b)[threadIdx.x];
    __half2 h0 = __floats2half2_rn((v.x - mu) * rstd * gg.x + bb.x,
                                   (v.y - mu) * rstd * gg.y + bb.y);
    __half2 h1 = __floats2half2_rn((v.z - mu) * rstd * gg.z + bb.z,
                                   (v.w - mu) * rstd * gg.w + bb.w);
    __half2* op = (__half2*)(out + (size_t)row * C_);
    op[threadIdx.x * 2 + 0] = h0;
    op[threadIdx.x * 2 + 1] = h1;
}

// ---------------------------------------------------------------------------
// FP16 tensor-core GEMM with ldmatrix fragment loads.
// C[M,Nc] = A[M,K] @ Bt[Nc,K]^T + bias (+res)(+gelu)
// BM=BN=128, BK=32, 256 threads (8 warps, 2x4), warp tile 64x32 via m16n8k16.
// Smem row: 16 data u32 + 4 pad (80B stride) -> LDSM conflict-free.
// ---------------------------------------------------------------------------
#define GBK 32
#define GSU 20          // u32 stride per row

__global__ __launch_bounds__(256, 2) void mma_gemm(
    const __half* __restrict__ A, const __half* __restrict__ Bt,
    const float* __restrict__ bias, const float* __restrict__ res,
    float* __restrict__ Cf, __half* __restrict__ Ch,
    int M, int Nc, int K, int do_gelu)
{
    __shared__ __align__(16) u32 shA[2][128 * GSU];
    __shared__ __align__(16) u32 shB[2][128 * GSU];

    const int tid = threadIdx.x;
    const int bm = blockIdx.y * 128;
    const int bn = blockIdx.x * 128;
    const int warp = tid >> 5, lane = tid & 31;
    const int wr = warp >> 2, wc = warp & 3;        // 2 x 4 warp grid
    const int grp = lane >> 2, tig = lane & 3;

    // global->smem chunk mapping: 512 16B chunks per tile, 2 per thread
    const int r0 = tid >> 1;            // rows 0..127
    const int c0 = (tid & 1) * 2;       // chunk pairs: c0, c0+1  (4 chunks/row)

    const __half* Ag = A  + (size_t)(bm + r0) * K + c0 * 8;
    const __half* Bg = Bt + (size_t)(bn + r0) * K + c0 * 8;
    u32 sAd0 = smem_u32(&shA[0][r0 * GSU + c0 * 4]);
    u32 sAd1 = smem_u32(&shA[1][r0 * GSU + c0 * 4]);
    u32 sBd0 = smem_u32(&shB[0][r0 * GSU + c0 * 4]);
    u32 sBd1 = smem_u32(&shB[1][r0 * GSU + c0 * 4]);

    // ldmatrix lane addressing
    const int rA = ((lane >> 3) & 1) * 8 + (lane & 7);
    const int cA = (lane >> 4) * 4;
    const int rB = (lane >> 4) * 8 + (lane & 7);
    const int cB = ((lane >> 3) & 1) * 4;
    u32 aoff[4], boff[2];
    #pragma unroll
    for (int mt = 0; mt < 4; mt++)
        aoff[mt] = ((wr * 64 + mt * 16 + rA) * GSU + cA) * 4;
    #pragma unroll
    for (int p = 0; p < 2; p++)
        boff[p] = ((wc * 32 + p * 16 + rB) * GSU + cB) * 4;
    const u32 shA0 = smem_u32(&shA[0][0]), shA1 = smem_u32(&shA[1][0]);
    const u32 shB0 = smem_u32(&shB[0][0]), shB1 = smem_u32(&shB[1][0]);

    float acc[4][4][4];
    #pragma unroll
    for (int mt = 0; mt < 4; mt++)
        #pragma unroll
        for (int nt = 0; nt < 4; nt++)
            #pragma unroll
            for (int r = 0; r < 4; r++) acc[mt][nt][r] = 0.0f;

    // prologue: stage 0
    cp_async16(sAd0, Ag);      cp_async16(sAd0 + 16, Ag + 8);
    cp_async16(sBd0, Bg);      cp_async16(sBd0 + 16, Bg + 8);
    CP_COMMIT();

    const int NT = K / GBK;
    for (int t = 0; t < NT; t++) {
        CP_WAIT(0);
        __syncthreads();

        if (t + 1 < NT) {
            int k0 = (t + 1) * GBK;
            u32 sa = ((t + 1) & 1) ? sAd1 : sAd0;
            u32 sb = ((t + 1) & 1) ? sBd1 : sBd0;
            cp_async16(sa, Ag + k0);      cp_async16(sa + 16, Ag + k0 + 8);
            cp_async16(sb, Bg + k0);      cp_async16(sb + 16, Bg + k0 + 8);
            CP_COMMIT();
        }

        const u32 baseA = (t & 1) ? shA1 : shA0;
        const u32 baseB = (t & 1) ? shB1 : shB0;
        #pragma unroll
        for (int kk = 0; kk < 2; kk++) {           // two k16 steps
            const u32 ko = kk * 32;                // bytes (8 u32)
            u32 fragA[4][4];
            u32 fragB[2][4];
            #pragma unroll
            for (int mt = 0; mt < 4; mt++)
                LDSM_X4(fragA[mt], baseA + aoff[mt] + ko);
            #pragma unroll
            for (int p = 0; p < 2; p++)
                LDSM_X4(fragB[p], baseB + boff[p] + ko);
            #pragma unroll
            for (int mt = 0; mt < 4; mt++) {
                #pragma unroll
                for (int nt = 0; nt < 4; nt++)
                    MMA_F16(acc[mt][nt], fragA[mt],
                            fragB[nt >> 1][(nt & 1) * 2],
                            fragB[nt >> 1][(nt & 1) * 2 + 1]);
            }
        }
    }

    // epilogue
    #pragma unroll
    for (int mt = 0; mt < 4; mt++) {
        #pragma unroll
        for (int i = 0; i < 2; i++) {
            int row = bm + wr * 64 + mt * 16 + grp + i * 8;
            #pragma unroll
            for (int nt = 0; nt < 4; nt++) {
                int col = bn + wc * 32 + nt * 8 + 2 * tig;
                float v0 = acc[mt][nt][2 * i + 0] + bias[col];
                float v1 = acc[mt][nt][2 * i + 1] + bias[col + 1];
                if (res) {
                    const float* rp = res + (size_t)row * Nc + col;
                    v0 += rp[0]; v1 += rp[1];
                }
                if (do_gelu) {
                    v0 = v0 * normcdff(v0);
                    v1 = v1 * normcdff(v1);
                }
                if (Ch) {
                    *(__half2*)(Ch + (size_t)row * Nc + col) = __floats2half2_rn(v0, v1);
                } else {
                    *(float2*)(Cf + (size_t)row * Nc + col) = make_float2(v0, v1);
                }
            }
        }
    }
}

// ---------------------------------------------------------------------------
// Fused window attention: fp16 qkv in, fp32 math, fp16 out
// ---------------------------------------------------------------------------
__global__ __launch_bounds__(128) void attn_kernel(
    const __half* __restrict__ qkv, const float* __restrict__ rel_bias,
    __half* __restrict__ ao)
{
    int w = blockIdx.x;          // 0..1023
    int head = blockIdx.y;       // 0..15
    int b  = w >> 6;
    int wi = w & 63;
    int wr = wi >> 3;
    int wc = wi & 7;
    int tid = threadIdx.x;

    __shared__ float qs[N_][HD_];
    __shared__ float kT[HD_][N_];
    __shared__ float vT[HD_][N_];
    __shared__ float S [N_][N_];

    int base_col = head * HD_;

    for (int idx = tid; idx < N_ * 4; idx += 128) {
        int n = idx >> 2, f = (idx & 3) * 8;
        int ir = n / 7, ic = n - (n / 7) * 7;
        size_t row = (size_t)(b * 56 + wr * 7 + ir) * 56 + (wc * 7 + ic);
        size_t off = row * QKVC_ + base_col + f;
        const __half2* qp = (const __half2*)(qkv + off);
        const __half2* kp = (const __half2*)(qkv + off + 512);
        const __half2* vp = (const __half2*)(qkv + off + 1024);
        #pragma unroll
        for (int j = 0; j < 4; j++) {
            float2 qf = __half22float2(qp[j]);
            qs[n][f + 2 * j]     = qf.x;
            qs[n][f + 2 * j + 1] = qf.y;
            float2 kf = __half22float2(kp[j]);
            kT[f + 2 * j][n]     = kf.x;
            kT[f + 2 * j + 1][n] = kf.y;
            float2 vf = __half22float2(vp[j]);
            vT[f + 2 * j][n]     = vf.x;
            vT[f + 2 * j + 1][n] = vf.y;
        }
    }
    __syncthreads();

    const float* rb = rel_bias + head * (N_ * N_);
    for (int idx = tid; idx < N_ * N_; idx += 128) {
        int i = idx / N_, j = idx - i * N_;
        float s = 0.0f;
        #pragma unroll
        for (int d = 0; d < HD_; d++) s = fmaf(qs[i][d], kT[d][j], s);
        S[i][j] = s * SCALE_ + rb[idx];
    }
    __syncthreads();

    int warp = tid >> 5, lane = tid & 31;
    for (int i = warp; i < N_; i += 4) {
        float m = -1e30f;
        for (int j = lane; j < N_; j += 32) m = fmaxf(m, S[i][j]);
        #pragma unroll
        for (int o = 16; o; o >>= 1) m = fmaxf(m, __shfl_xor_sync(0xffffffffu, m, o));
        float sum = 0.0f;
        for (int j = lane; j < N_; j += 32) {
            float e = __expf(S[i][j] - m);
            S[i][j] = e;
            sum += e;
        }
        #pragma unroll
        for (int o = 16; o; o >>= 1) sum += __shfl_xor_sync(0xffffffffu, sum, o);
        float inv = 1.0f / sum;
        for (int j = lane; j < N_; j += 32) S[i][j] *= inv;
    }
    __syncthreads();

    for (int idx = tid; idx < N_ * HD_; idx += 128) {
        int i = idx >> 5, d = idx & 31;
        float s = 0.0f;
        #pragma unroll
        for (int j = 0; j < N_; j++) s = fmaf(S[i][j], vT[d][j], s);
        int ir = i / 7, ic = i - (i / 7) * 7;
        size_t row = (size_t)(b * 56 + wr * 7 + ir) * 56 + (wc * 7 + ic);
        ao[row * C_ + base_col + d] = __float2half_rn(s);
    }
}

// ---------------------------------------------------------------------------
// Launch
// ---------------------------------------------------------------------------
extern "C" void kernel_launch(void* const* d_in, const int* in_sizes, int n_in,
                              void* d_out, int out_size)
{
    const float* x    = (const float*)d_in[0];
    const float* Wq   = (const float*)d_in[1];
    const float* bq   = (const float*)d_in[2];
    const float* Wk   = (const float*)d_in[3];
    const float* bk   = (const float*)d_in[4];
    const float* Wv   = (const float*)d_in[5];
    const float* bv   = (const float*)d_in[6];
    const float* Wp   = (const float*)d_in[7];
    const float* bp   = (const float*)d_in[8];
    const float* rel  = (const float*)d_in[9];
    const float* g1   = (const float*)d_in[10];
    const float* b1   = (const float*)d_in[11];
    const float* g2   = (const float*)d_in[12];
    const float* b2   = (const float*)d_in[13];
    const float* W1   = (const float*)d_in[14];
    const float* bfc1 = (const float*)d_in[15];
    const float* W2   = (const float*)d_in[16];
    const float* bfc2 = (const float*)d_in[17];
    float* out = (float*)d_out;

    __half *h, *qkv, *ao, *hid, *wtqkv, *wtp, *wt1, *wt2;
    float *x2, *bqkv;
    cudaGetSymbolAddress((void**)&h,     g_h);
    cudaGetSymbolAddress((void**)&qkv,   g_qkv);
    cudaGetSymbolAddress((void**)&ao,    g_ao);
    cudaGetSymbolAddress((void**)&x2,    g_x2);
    cudaGetSymbolAddress((void**)&hid,   g_hid);
    cudaGetSymbolAddress((void**)&wtqkv, g_wtqkv);
    cudaGetSymbolAddress((void**)&wtp,   g_wtp);
    cudaGetSymbolAddress((void**)&wt1,   g_wt1);
    cudaGetSymbolAddress((void**)&wt2,   g_wt2);
    cudaGetSymbolAddress((void**)&bqkv,  g_bqkv);

    // 0. Weight transposes (K-major, fp16) + bias packing
    dim3 tb(32, 8);
    transpose_kernel<<<dim3(C_ / 32, C_ / 32), tb>>>(Wq, wtqkv,             C_, C_);
    transpose_kernel<<<dim3(C_ / 32, C_ / 32), tb>>>(Wk, wtqkv + 512 * C_,  C_, C_);
    transpose_kernel<<<dim3(C_ / 32, C_ / 32), tb>>>(Wv, wtqkv + 1024 * C_, C_, C_);
    transpose_kernel<<<dim3(C_ / 32, C_ / 32), tb>>>(Wp, wtp, C_, C_);
    transpose_kernel<<<dim3(HID_ / 32, C_ / 32), tb>>>(W1, wt1, C_, HID_);
    transpose_kernel<<<dim3(C_ / 32, HID_ / 32), tb>>>(W2, wt2, HID_, C_);
    pack_bias_kernel<<<6, 256>>>(bq, bk, bv, bqkv);

    // 1. LN1 -> h (fp16)
    ln_kernel<<<ROWS_, 128>>>(x, g1, b1, h);

    // 2. Fused QKV projection (N = 1536) -> qkv (fp16)
    mma_gemm<<<dim3(QKVC_ / 128, ROWS_ / 128), 256>>>(
        h, wtqkv, bqkv, nullptr, nullptr, qkv, ROWS_, QKVC_, C_, 0);

    // 3. Windowed attention -> ao (fp16)
    attn_kernel<<<dim3(B_ * NW_, NH_), 128>>>(qkv, rel, ao);

    // 4. Output projection + residual: x2 = x + ao @ Wp + bp (fp32)
    mma_gemm<<<dim3(C_ / 128, ROWS_ / 128), 256>>>(
        ao, wtp, bp, x, x2, nullptr, ROWS_, C_, C_, 0);

    // 5. LN2 -> h (fp16)
    ln_kernel<<<ROWS_, 128>>>(x2, g2, b2, h);

    // 6. MLP fc1 + exact GELU -> hid (fp16)
    mma_gemm<<<dim3(HID_ / 128, ROWS_ / 128), 256>>>(
        h, wt1, bfc1, nullptr, nullptr, hid, ROWS_, HID_, C_, 1);

    // 7. MLP fc2 + residual -> out (fp32)
    mma_gemm<<<dim3(C_ / 128, ROWS_ / 128), 256>>>(
        hid, wt2, bfc2, x2, out, nullptr, ROWS_, C_, HID_, 0);
}

// round 9
// speedup vs baseline: 1.0450x; 1.0450x over previous
#include <cuda_runtime.h>
#include <cuda_fp16.h>
#include <math.h>

typedef unsigned int u32;

// Problem constants
#define B_   16
#define H_   56
#define W_   56
#define C_   512
#define WS_  7
#define NH_  16
#define HD_  32
#define HID_ 2048
#define N_   49
#define NW_  64
#define L_   (H_ * W_)          // 3136
#define ROWS_ (B_ * L_)         // 50176
#define QKVC_ 1536
#define SCALE_ 0.17677669529663687f
#define EPS_ 1e-5f

// Scratch (device globals: allocation-free)
__device__ __half g_h  [ROWS_ * C_];
__device__ __half g_qkv[ROWS_ * QKVC_];
__device__ __half g_ao [ROWS_ * C_];
__device__ float  g_x2 [ROWS_ * C_];
__device__ __half g_hid[ROWS_ * HID_];
__device__ __half g_wtqkv[QKVC_ * C_];   // [1536][512]  (Wq^T | Wk^T | Wv^T)
__device__ __half g_wtp  [C_ * C_];
__device__ __half g_wt1  [HID_ * C_];
__device__ __half g_wt2  [C_ * HID_];
__device__ float  g_bqkv [QKVC_];

// ---------------------------------------------------------------------------
// Helpers
// ---------------------------------------------------------------------------
__device__ __forceinline__ void cp_async16(u32 saddr, const void* gptr) {
    asm volatile("cp.async.cg.shared.global [%0], [%1], 16;" :: "r"(saddr), "l"(gptr));
}
#define CP_COMMIT() asm volatile("cp.async.commit_group;")
#define CP_WAIT(n)  asm volatile("cp.async.wait_group %0;" :: "n"(n))

#define MMA_F16(ac, ar, b0, b1)                                                 \
    asm volatile(                                                               \
        "mma.sync.aligned.m16n8k16.row.col.f32.f16.f16.f32 "                    \
        "{%0,%1,%2,%3},{%4,%5,%6,%7},{%8,%9},{%0,%1,%2,%3};"                    \
        : "+f"(ac[0]), "+f"(ac[1]), "+f"(ac[2]), "+f"(ac[3])                    \
        : "r"(ar[0]), "r"(ar[1]), "r"(ar[2]), "r"(ar[3]), "r"(b0), "r"(b1))

#define LDSM_X4(r, a)                                                           \
    asm volatile("ldmatrix.sync.aligned.m8n8.x4.shared.b16 {%0,%1,%2,%3}, [%4];"\
        : "=r"((r)[0]), "=r"((r)[1]), "=r"((r)[2]), "=r"((r)[3]) : "r"(a))

__device__ __forceinline__ u32 smem_u32(const void* p) {
    return (u32)__cvta_generic_to_shared(p);
}

// ---------------------------------------------------------------------------
// Batched QKV weight transpose + bias pack (one launch)
// grid (16,16,3), block (32,8)
// ---------------------------------------------------------------------------
__global__ __launch_bounds__(256) void transpose_qkv_kernel(
    const float* __restrict__ Wq, const float* __restrict__ Wk,
    const float* __restrict__ Wv,
    const float* __restrict__ bq, const float* __restrict__ bk,
    const float* __restrict__ bv,
    __half* __restrict__ dst, float* __restrict__ bdst)
{
    int z = blockIdx.z;
    const float* src = (z == 0) ? Wq : (z == 1) ? Wk : Wv;
    __half* d = dst + (size_t)z * 512 * C_;

    __shared__ float tile[32][33];
    int bx = blockIdx.x * 32, by = blockIdx.y * 32;
    int tx = threadIdx.x, ty = threadIdx.y;
    #pragma unroll
    for (int i = 0; i < 32; i += 8)
        tile[ty + i][tx] = src[(size_t)(by + ty + i) * C_ + bx + tx];
    __syncthreads();
    #pragma unroll
    for (int i = 0; i < 32; i += 8)
        d[(size_t)(bx + ty + i) * C_ + by + tx] = __float2half_rn(tile[tx][ty + i]);

    if (z == 0 && blockIdx.x == 0 && blockIdx.y == 0) {
        int t = ty * 32 + tx;
        for (int i = t; i < QKVC_; i += 256)
            bdst[i] = i < 512 ? bq[i] : (i < 1024 ? bk[i - 512] : bv[i - 1024]);
    }
}

// ---------------------------------------------------------------------------
// Transpose + fp16 convert: dst[Cc][R] = half(src[R][Cc]^T)
// ---------------------------------------------------------------------------
__global__ __launch_bounds__(256) void transpose_kernel(
    const float* __restrict__ src, __half* __restrict__ dst, int R, int Cc)
{
    __shared__ float tile[32][33];
    int bx = blockIdx.x * 32, by = blockIdx.y * 32;
    int tx = threadIdx.x, ty = threadIdx.y;   // 32 x 8
    #pragma unroll
    for (int i = 0; i < 32; i += 8)
        tile[ty + i][tx] = src[(size_t)(by + ty + i) * Cc + bx + tx];
    __syncthreads();
    #pragma unroll
    for (int i = 0; i < 32; i += 8)
        dst[(size_t)(bx + ty + i) * R + by + tx] = __float2half_rn(tile[tx][ty + i]);
}

// ---------------------------------------------------------------------------
// LayerNorm: fp32 in, fp16 out
// ---------------------------------------------------------------------------
__global__ __launch_bounds__(128) void ln_kernel(const float* __restrict__ x,
                                                 const float* __restrict__ g,
                                                 const float* __restrict__ b,
                                                 __half* __restrict__ out) {
    int row = blockIdx.x;
    const float4* xr = (const float4*)(x + (size_t)row * C_);
    float4 v = xr[threadIdx.x];
    float s  = v.x + v.y + v.z + v.w;
    float s2 = v.x * v.x + v.y * v.y + v.z * v.z + v.w * v.w;
    #pragma unroll
    for (int o = 16; o; o >>= 1) {
        s  += __shfl_xor_sync(0xffffffffu, s, o);
        s2 += __shfl_xor_sync(0xffffffffu, s2, o);
    }
    __shared__ float sm[4], sm2[4];
    int warp = threadIdx.x >> 5;
    if ((threadIdx.x & 31) == 0) { sm[warp] = s; sm2[warp] = s2; }
    __syncthreads();
    s  = sm[0] + sm[1] + sm[2] + sm[3];
    s2 = sm2[0] + sm2[1] + sm2[2] + sm2[3];
    float mu   = s * (1.0f / C_);
    float var  = s2 * (1.0f / C_) - mu * mu;
    float rstd = rsqrtf(var + EPS_);
    float4 gg = ((const float4*)g)[threadIdx.x];
    float4 bb = ((const float4*)b)[threadIdx.x];
    __half2 h0 = __floats2half2_rn((v.x - mu) * rstd * gg.x + bb.x,
                                   (v.y - mu) * rstd * gg.y + bb.y);
    __half2 h1 = __floats2half2_rn((v.z - mu) * rstd * gg.z + bb.z,
                                   (v.w - mu) * rstd * gg.w + bb.w);
    __half2* op = (__half2*)(out + (size_t)row * C_);
    op[threadIdx.x * 2 + 0] = h0;
    op[threadIdx.x * 2 + 1] = h1;
}

// ---------------------------------------------------------------------------
// FP16 tensor-core GEMM, 3-stage cp.async pipeline, ldmatrix fragments.
// C[M,Nc] = A[M,K] @ Bt[Nc,K]^T + bias (+res)(+gelu)
// BM=BN=128, BK=32, 256 threads (8 warps, 2x4), warp tile 64x32 via m16n8k16.
// Dynamic smem: 3 stages x (A,B) x 128 rows x 20 u32 (80B stride, LDSM clean).
// ---------------------------------------------------------------------------
#define GBK 32
#define GSU 20                       // u32 stride per row
#define STG_U32 (128 * GSU)          // u32 per matrix per stage
#define GEMM_SMEM (6 * STG_U32 * 4)  // 61440 bytes

__global__ __launch_bounds__(256, 2) void mma_gemm(
    const __half* __restrict__ A, const __half* __restrict__ Bt,
    const float* __restrict__ bias, const float* __restrict__ res,
    float* __restrict__ Cf, __half* __restrict__ Ch,
    int M, int Nc, int K, int do_gelu)
{
    extern __shared__ __align__(16) u32 dynsm[];

    const int tid = threadIdx.x;
    const int bm = blockIdx.y * 128;
    const int bn = blockIdx.x * 128;
    const int warp = tid >> 5, lane = tid & 31;
    const int wr = warp >> 2, wc = warp & 3;        // 2 x 4 warp grid
    const int grp = lane >> 2, tig = lane & 3;

    // global->smem chunk mapping: 512 16B chunks per matrix per stage, 2/thread
    const int r0 = tid >> 1;            // rows 0..127
    const int c0 = (tid & 1) * 2;       // chunks c0, c0+1

    const __half* Ag = A  + (size_t)(bm + r0) * K + c0 * 8;
    const __half* Bg = Bt + (size_t)(bn + r0) * K + c0 * 8;
    const u32 stoff = (r0 * GSU + c0 * 4) * 4;   // store offset in bytes

    const u32 base = smem_u32(dynsm);
    // rotating stage bases (A and B)
    u32 bA0 = base;
    u32 bA1 = base + STG_U32 * 4;
    u32 bA2 = base + 2 * STG_U32 * 4;
    u32 bB0 = base + 3 * STG_U32 * 4;
    u32 bB1 = base + 4 * STG_U32 * 4;
    u32 bB2 = base + 5 * STG_U32 * 4;

    // ldmatrix lane addressing (byte offsets relative to stage base)
    const int rA = ((lane >> 3) & 1) * 8 + (lane & 7);
    const int cA = (lane >> 4) * 4;
    const int rB = (lane >> 4) * 8 + (lane & 7);
    const int cB = ((lane >> 3) & 1) * 4;
    u32 aoff[4], boff[2];
    #pragma unroll
    for (int mt = 0; mt < 4; mt++)
        aoff[mt] = ((wr * 64 + mt * 16 + rA) * GSU + cA) * 4;
    #pragma unroll
    for (int p = 0; p < 2; p++)
        boff[p] = ((wc * 32 + p * 16 + rB) * GSU + cB) * 4;

    float acc[4][4][4];
    #pragma unroll
    for (int mt = 0; mt < 4; mt++)
        #pragma unroll
        for (int nt = 0; nt < 4; nt++)
            #pragma unroll
            for (int r = 0; r < 4; r++) acc[mt][nt][r] = 0.0f;

    // prologue: stages 0 and 1
    cp_async16(bA0 + stoff, Ag);       cp_async16(bA0 + stoff + 16, Ag + 8);
    cp_async16(bB0 + stoff, Bg);       cp_async16(bB0 + stoff + 16, Bg + 8);
    CP_COMMIT();
    cp_async16(bA1 + stoff, Ag + GBK); cp_async16(bA1 + stoff + 16, Ag + GBK + 8);
    cp_async16(bB1 + stoff, Bg + GBK); cp_async16(bB1 + stoff + 16, Bg + GBK + 8);
    CP_COMMIT();

    const int NT = K / GBK;
    for (int t = 0; t < NT; t++) {
        CP_WAIT(1);
        __syncthreads();

        if (t + 2 < NT) {
            int k0 = (t + 2) * GBK;
            cp_async16(bA2 + stoff, Ag + k0);      cp_async16(bA2 + stoff + 16, Ag + k0 + 8);
            cp_async16(bB2 + stoff, Bg + k0);      cp_async16(bB2 + stoff + 16, Bg + k0 + 8);
        }
        CP_COMMIT();   // possibly empty group; keeps wait bookkeeping uniform

        #pragma unroll
        for (int kk = 0; kk < 2; kk++) {           // two k16 steps
            const u32 ko = kk * 32;                // bytes (8 u32)
            u32 fragA[4][4];
            u32 fragB[2][4];
            #pragma unroll
            for (int mt = 0; mt < 4; mt++)
                LDSM_X4(fragA[mt], bA0 + aoff[mt] + ko);
            #pragma unroll
            for (int p = 0; p < 2; p++)
                LDSM_X4(fragB[p], bB0 + boff[p] + ko);
            #pragma unroll
            for (int mt = 0; mt < 4; mt++) {
                #pragma unroll
                for (int nt = 0; nt < 4; nt++)
                    MMA_F16(acc[mt][nt], fragA[mt],
                            fragB[nt >> 1][(nt & 1) * 2],
                            fragB[nt >> 1][(nt & 1) * 2 + 1]);
            }
        }

        // rotate stages
        u32 tA = bA0; bA0 = bA1; bA1 = bA2; bA2 = tA;
        u32 tB = bB0; bB0 = bB1; bB1 = bB2; bB2 = tB;
    }

    // epilogue
    #pragma unroll
    for (int mt = 0; mt < 4; mt++) {
        #pragma unroll
        for (int i = 0; i < 2; i++) {
            int row = bm + wr * 64 + mt * 16 + grp + i * 8;
            #pragma unroll
            for (int nt = 0; nt < 4; nt++) {
                int col = bn + wc * 32 + nt * 8 + 2 * tig;
                float v0 = acc[mt][nt][2 * i + 0] + bias[col];
                float v1 = acc[mt][nt][2 * i + 1] + bias[col + 1];
                if (res) {
                    const float* rp = res + (size_t)row * Nc + col;
                    v0 += rp[0]; v1 += rp[1];
                }
                if (do_gelu) {
                    v0 = v0 * normcdff(v0);
                    v1 = v1 * normcdff(v1);
                }
                if (Ch) {
                    *(__half2*)(Ch + (size_t)row * Nc + col) = __floats2half2_rn(v0, v1);
                } else {
                    *(float2*)(Cf + (size_t)row * Nc + col) = make_float2(v0, v1);
                }
            }
        }
    }
}

// ---------------------------------------------------------------------------
// Fused window attention: fp16 qkv in, fp32 math, fp16 out
// ---------------------------------------------------------------------------
__global__ __launch_bounds__(128) void attn_kernel(
    const __half* __restrict__ qkv, const float* __restrict__ rel_bias,
    __half* __restrict__ ao)
{
    int w = blockIdx.x;          // 0..1023
    int head = blockIdx.y;       // 0..15
    int b  = w >> 6;
    int wi = w & 63;
    int wr = wi >> 3;
    int wc = wi & 7;
    int tid = threadIdx.x;

    __shared__ float qs[N_][HD_];
    __shared__ float kT[HD_][N_];
    __shared__ float vT[HD_][N_];
    __shared__ float S [N_][N_];

    int base_col = head * HD_;

    for (int idx = tid; idx < N_ * 4; idx += 128) {
        int n = idx >> 2, f = (idx & 3) * 8;
        int ir = n / 7, ic = n - (n / 7) * 7;
        size_t row = (size_t)(b * 56 + wr * 7 + ir) * 56 + (wc * 7 + ic);
        size_t off = row * QKVC_ + base_col + f;
        const __half2* qp = (const __half2*)(qkv + off);
        const __half2* kp = (const __half2*)(qkv + off + 512);
        const __half2* vp = (const __half2*)(qkv + off + 1024);
        #pragma unroll
        for (int j = 0; j < 4; j++) {
            float2 qf = __half22float2(qp[j]);
            qs[n][f + 2 * j]     = qf.x;
            qs[n][f + 2 * j + 1] = qf.y;
            float2 kf = __half22float2(kp[j]);
            kT[f + 2 * j][n]     = kf.x;
            kT[f + 2 * j + 1][n] = kf.y;
            float2 vf = __half22float2(vp[j]);
            vT[f + 2 * j][n]     = vf.x;
            vT[f + 2 * j + 1][n] = vf.y;
        }
    }
    __syncthreads();

    const float* rb = rel_bias + head * (N_ * N_);
    for (int idx = tid; idx < N_ * N_; idx += 128) {
        int i = idx / N_, j = idx - i * N_;
        float s = 0.0f;
        #pragma unroll
        for (int d = 0; d < HD_; d++) s = fmaf(qs[i][d], kT[d][j], s);
        S[i][j] = s * SCALE_ + rb[idx];
    }
    __syncthreads();

    int warp = tid >> 5, lane = tid & 31;
    for (int i = warp; i < N_; i += 4) {
        float m = -1e30f;
        for (int j = lane; j < N_; j += 32) m = fmaxf(m, S[i][j]);
        #pragma unroll
        for (int o = 16; o; o >>= 1) m = fmaxf(m, __shfl_xor_sync(0xffffffffu, m, o));
        float sum = 0.0f;
        for (int j = lane; j < N_; j += 32) {
            float e = __expf(S[i][j] - m);
            S[i][j] = e;
            sum += e;
        }
        #pragma unroll
        for (int o = 16; o; o >>= 1) sum += __shfl_xor_sync(0xffffffffu, sum, o);
        float inv = 1.0f / sum;
        for (int j = lane; j < N_; j += 32) S[i][j] *= inv;
    }
    __syncthreads();

    for (int idx = tid; idx < N_ * HD_; idx += 128) {
        int i = idx >> 5, d = idx & 31;
        float s = 0.0f;
        #pragma unroll
        for (int j = 0; j < N_; j++) s = fmaf(S[i][j], vT[d][j], s);
        int ir = i / 7, ic = i - (i / 7) * 7;
        size_t row = (size_t)(b * 56 + wr * 7 + ir) * 56 + (wc * 7 + ic);
        ao[row * C_ + base_col + d] = __float2half_rn(s);
    }
}

// ---------------------------------------------------------------------------
// Launch
// ---------------------------------------------------------------------------
extern "C" void kernel_launch(void* const* d_in, const int* in_sizes, int n_in,
                              void* d_out, int out_size)
{
    const float* x    = (const float*)d_in[0];
    const float* Wq   = (const float*)d_in[1];
    const float* bq   = (const float*)d_in[2];
    const float* Wk   = (const float*)d_in[3];
    const float* bk   = (const float*)d_in[4];
    const float* Wv   = (const float*)d_in[5];
    const float* bv   = (const float*)d_in[6];
    const float* Wp   = (const float*)d_in[7];
    const float* bp   = (const float*)d_in[8];
    const float* rel  = (const float*)d_in[9];
    const float* g1   = (const float*)d_in[10];
    const float* b1   = (const float*)d_in[11];
    const float* g2   = (const float*)d_in[12];
    const float* b2   = (const float*)d_in[13];
    const float* W1   = (const float*)d_in[14];
    const float* bfc1 = (const float*)d_in[15];
    const float* W2   = (const float*)d_in[16];
    const float* bfc2 = (const float*)d_in[17];
    float* out = (float*)d_out;

    __half *h, *qkv, *ao, *hid, *wtqkv, *wtp, *wt1, *wt2;
    float *x2, *bqkv;
    cudaGetSymbolAddress((void**)&h,     g_h);
    cudaGetSymbolAddress((void**)&qkv,   g_qkv);
    cudaGetSymbolAddress((void**)&ao,    g_ao);
    cudaGetSymbolAddress((void**)&x2,    g_x2);
    cudaGetSymbolAddress((void**)&hid,   g_hid);
    cudaGetSymbolAddress((void**)&wtqkv, g_wtqkv);
    cudaGetSymbolAddress((void**)&wtp,   g_wtp);
    cudaGetSymbolAddress((void**)&wt1,   g_wt1);
    cudaGetSymbolAddress((void**)&wt2,   g_wt2);
    cudaGetSymbolAddress((void**)&bqkv,  g_bqkv);

    cudaFuncSetAttribute(mma_gemm, cudaFuncAttributeMaxDynamicSharedMemorySize,
                         GEMM_SMEM);

    dim3 tb(32, 8);
    // 0: batched QKV transposes + bias pack
    transpose_qkv_kernel<<<dim3(16, 16, 3), tb>>>(Wq, Wk, Wv, bq, bk, bv,
                                                  wtqkv, bqkv);
    // 1-3: remaining weight transposes
    transpose_kernel<<<dim3(C_ / 32, C_ / 32), tb>>>(Wp, wtp, C_, C_);
    transpose_kernel<<<dim3(HID_ / 32, C_ / 32), tb>>>(W1, wt1, C_, HID_);
    transpose_kernel<<<dim3(C_ / 32, HID_ / 32), tb>>>(W2, wt2, HID_, C_);

    // 4: LN1 -> h (fp16)
    ln_kernel<<<ROWS_, 128>>>(x, g1, b1, h);

    // 5: Fused QKV projection (N = 1536) -> qkv (fp16)   [ncu profiles this]
    mma_gemm<<<dim3(QKVC_ / 128, ROWS_ / 128), 256, GEMM_SMEM>>>(
        h, wtqkv, bqkv, nullptr, nullptr, qkv, ROWS_, QKVC_, C_, 0);

    // 6: Windowed attention -> ao (fp16)
    attn_kernel<<<dim3(B_ * NW_, NH_), 128>>>(qkv, rel, ao);

    // 7: Output projection + residual: x2 = x + ao @ Wp + bp (fp32)
    mma_gemm<<<dim3(C_ / 128, ROWS_ / 128), 256, GEMM_SMEM>>>(
        ao, wtp, bp, x, x2, nullptr, ROWS_, C_, C_, 0);

    // 8: LN2 -> h (fp16)
    ln_kernel<<<ROWS_, 128>>>(x2, g2, b2, h);

    // 9: MLP fc1 + exact GELU -> hid (fp16)
    mma_gemm<<<dim3(HID_ / 128, ROWS_ / 128), 256, GEMM_SMEM>>>(
        h, wt1, bfc1, nullptr, nullptr, hid, ROWS_, HID_, C_, 1);

    // 10: MLP fc2 + residual -> out (fp32)
    mma_gemm<<<dim3(C_ / 128, ROWS_ / 128), 256, GEMM_SMEM>>>(
        hid, wt2, bfc2, x2, out, nullptr, ROWS_, C_, HID_, 0);
}